// round 12
// baseline (speedup 1.0000x reference)
#include <cuda_runtime.h>

// Dice score: input (B=4, C=5, 128^3) fp32 logits, target (4, 128^3) int ids.
// pred = argmax over C; per-batch/class counts of pred/target/intersection
// (classes 1..4); dice = (2I+eps)/(P+T+eps); mean of 16 values -> out[0].
//
// Single kernel, grid = 5*148 = 740 blocks, 5 resident CTAs per SM.
// Grid is PARTITIONED by batch (185 blocks each) so the hot loop is a pure
// branch-free stream over float4 "quads" (no batch-switch test inside),
// letting ptxas front-batch loads for high MLP. Per-thread byte-packed
// counters -> one 16-bit-field warp REDUX flush at loop end -> shared
// atomics -> returning global atomics (no __threadfence / L1 flush) ->
// ticket last-block finalize. Last block re-zeroes scratch so
// "scratch == 0 at entry" holds for every graph replay.

#define NB 4
#define NC 5
#define BQ   (1u << 19)                  // float4-quads per batch
#define TPB 256
#define BPB  185                         // blocks per batch
#define NBLOCKS (NB * BPB)               // 740 = 148*5: one balanced wave
#define QSTRIDE ((unsigned)BPB * TPB)    // 47360 quads per step within batch

// flat: [b][kind*4 + (c-1)], kind 0=pred,1=tgt,2=inter. Zero at entry.
__device__ int g_cnt[NB * 12];
__device__ unsigned g_ticket;

__global__ void __launch_bounds__(TPB, 5) k_count(const float* __restrict__ inp,
                                                  const void* __restrict__ tgt,
                                                  float* __restrict__ out) {
    // s_pack[kind*2 + h]: 16-bit fields, h=0 -> classes 1,3; h=1 -> 2,4
    __shared__ unsigned s_pack[6];
    __shared__ int s_is64;
    __shared__ int s_last;
    __shared__ int s_fin[NB * 12];
    volatile __shared__ int s_sink[12];
    const int tid  = threadIdx.x;
    const int lane = tid & 31;

    if (tid < 6) s_pack[tid] = 0;
    if (tid < 32) {
        // dtype probe: int32 read as int64 has a class id in the high word
        // whenever that word != 0; P(first 32 high words all zero) ~ (1/5)^32.
        long long v = ((const long long*)tgt)[tid];
        unsigned bad = __ballot_sync(0xffffffffu, v < 0 || v > (NC - 1));
        if (tid == 0) s_is64 = (bad == 0u);
    }
    __syncthreads();

    const int is64 = s_is64;
    const int b    = (int)(blockIdx.x) / BPB;             // block-constant batch
    const int blkb = (int)(blockIdx.x) - b * BPB;
    const unsigned tid0 = (unsigned)blkb * TPB + tid;     // quad offset in batch

    const float4*    in4 = (const float4*)inp + (size_t)b * (NC * BQ);
    const int4*      tg4 = (const int4*)tgt + (size_t)b * BQ;
    const longlong2* tg8 = (const longlong2*)tgt + (size_t)b * BQ * 2;

    // byte-packed counters; byte (c-1) counts class c. <= 12*4 = 48 per byte.
    unsigned pp = 0u, tp = 0u, ip = 0u;

    #pragma unroll 4
    for (unsigned q = tid0; q < BQ; q += QSTRIDE) {
        // ---- targets: 4 positions ----
        int tv[4];
        if (is64) {
            longlong2 ta = __ldcs(tg8 + 2u * q);
            longlong2 tb = __ldcs(tg8 + 2u * q + 1u);
            tv[0] = (int)ta.x; tv[1] = (int)ta.y; tv[2] = (int)tb.x; tv[3] = (int)tb.y;
        } else {
            int4 t4 = __ldcs(tg4 + q);
            tv[0] = t4.x; tv[1] = t4.y; tv[2] = t4.z; tv[3] = t4.w;
        }

        // ---- logits: 5 classes x float4 (streaming) ----
        float va[NC][4];
        #pragma unroll
        for (int c = 0; c < NC; c++) {
            float4 v = __ldcs(in4 + q + (unsigned)c * BQ);
            va[c][0] = v.x; va[c][1] = v.y; va[c][2] = v.z; va[c][3] = v.w;
        }

        // ---- per position: max + predicated packed increments ----
        #pragma unroll
        for (int k = 0; k < 4; k++) {
            const float f1 = va[1][k], f2 = va[2][k],
                        f3 = va[3][k], f4 = va[4][k];
            const float m = fmaxf(fmaxf(fmaxf(va[0][k], f1), fmaxf(f2, f3)), f4);
            const int t = tv[k];

            if (f1 == m) pp += 1u;
            if (f2 == m) pp += 1u << 8;
            if (f3 == m) pp += 1u << 16;
            if (f4 == m) pp += 1u << 24;

            if (t) tp += 1u << ((t - 1) * 8);

            if (f1 == m && t == 1) ip += 1u;
            if (f2 == m && t == 2) ip += 1u << 8;
            if (f3 == m && t == 3) ip += 1u << 16;
            if (f4 == m && t == 4) ip += 1u << 24;
        }
    }

    // warp reduction: bytes -> 16-bit fields (warp sum <= 1536), REDUX
    {
        unsigned v[6];
        v[0] = pp & 0x00FF00FFu;  v[1] = (pp >> 8) & 0x00FF00FFu;
        v[2] = tp & 0x00FF00FFu;  v[3] = (tp >> 8) & 0x00FF00FFu;
        v[4] = ip & 0x00FF00FFu;  v[5] = (ip >> 8) & 0x00FF00FFu;
        #pragma unroll
        for (int i = 0; i < 6; i++)
            v[i] = __reduce_add_sync(0xffffffffu, v[i]);
        if (lane == 0) {
            #pragma unroll
            for (int i = 0; i < 6; i++) atomicAdd(&s_pack[i], v[i]);
        }
    }
    __syncthreads();

    // block -> global: returning atomics (completion = L2 updated), no fence
    if (tid < 12) {
        const int kind = tid >> 2;            // 0=pred,1=tgt,2=inter
        const int ci   = tid & 3;             // class-1
        const unsigned pk = s_pack[kind * 2 + (ci & 1)];
        const int cnt = (int)((pk >> (16 * (ci >> 1))) & 0xFFFFu);
        const int ret = atomicAdd(&g_cnt[b * 12 + tid], cnt);
        s_sink[tid] = ret;                    // consume: waits for ATOMG return
    }
    __syncthreads();

    // last-block election (all 12 adds of every arrived block are L2-complete)
    if (tid == 0) s_last = (atomicAdd(&g_ticket, 1u) == NBLOCKS - 1);
    __syncthreads();

    if (s_last) {
        if (tid < NB * 12) {
            s_fin[tid] = atomicAdd(&g_cnt[tid], 0);   // L2-coherent read
            g_cnt[tid] = 0;                           // zero-at-entry invariant
        }
        if (tid == 0) g_ticket = 0u;
        __syncthreads();
        if (tid == 0) {
            float acc = 0.0f;
            #pragma unroll
            for (int bb = 0; bb < NB; bb++) {
                #pragma unroll
                for (int ci = 0; ci < 4; ci++) {
                    const float I = (float)s_fin[bb * 12 + 8 + ci];
                    const float U = (float)(s_fin[bb * 12 + ci] +
                                            s_fin[bb * 12 + 4 + ci]);
                    acc += (2.0f * I + 1e-5f) / (U + 1e-5f);
                }
            }
            out[0] = acc * (1.0f / 16.0f);
        }
    }
}

extern "C" void kernel_launch(void* const* d_in, const int* in_sizes, int n_in,
                              void* d_out, int out_size) {
    const float* inp = (const float*)d_in[0];
    const void*  tgt = d_in[1];
    float* out = (float*)d_out;
    (void)in_sizes; (void)n_in; (void)out_size;

    k_count<<<NBLOCKS, TPB>>>(inp, tgt, out);
}

// round 13
// speedup vs baseline: 1.0557x; 1.0557x over previous
#include <cuda_runtime.h>

// Dice score: input (B=4, C=5, 128^3) fp32 logits, target (4, 128^3) int ids.
// pred = argmax over C; per-batch/class counts of pred/target/intersection
// (classes 1..4); dice = (2I+eps)/(P+T+eps); mean of 16 values -> out[0].
//
// Single kernel, grid = 4*148 = 592 blocks, 4 resident CTAs per SM (one
// balanced wave). Grid PARTITIONED by batch (148 blocks each) so the hot
// loop is a pure branch-free stream over float4 "quads" — no batch test,
// no convergence barriers inside. Per-thread byte-packed counters -> one
// 16-bit-field warp REDUX flush -> shared atomics -> returning global
// atomics (no __threadfence / L1 flush) -> ticket last-block finalize.
// Last block re-zeroes scratch so "scratch == 0 at entry" holds for every
// graph replay.

#define NB 4
#define NC 5
#define BQ   (1u << 19)                  // float4-quads per batch
#define TPB 256
#define BPB  148                         // blocks per batch
#define NBLOCKS (NB * BPB)               // 592 = 148*4: one balanced wave
#define QSTRIDE ((unsigned)BPB * TPB)    // 37888 quads per step within batch

// flat: [b][kind*4 + (c-1)], kind 0=pred,1=tgt,2=inter. Zero at entry.
__device__ int g_cnt[NB * 12];
__device__ unsigned g_ticket;

__global__ void __launch_bounds__(TPB, 4) k_count(const float* __restrict__ inp,
                                                  const void* __restrict__ tgt,
                                                  float* __restrict__ out) {
    // s_pack[kind*2 + h]: 16-bit fields, h=0 -> classes 1,3; h=1 -> 2,4
    __shared__ unsigned s_pack[6];
    __shared__ int s_is64;
    __shared__ int s_last;
    __shared__ int s_fin[NB * 12];
    volatile __shared__ int s_sink[12];
    const int tid  = threadIdx.x;
    const int lane = tid & 31;

    if (tid < 6) s_pack[tid] = 0;
    if (tid < 32) {
        // dtype probe: int32 read as int64 has a class id in the high word
        // whenever that word != 0; P(first 32 high words all zero) ~ (1/5)^32.
        long long v = ((const long long*)tgt)[tid];
        unsigned bad = __ballot_sync(0xffffffffu, v < 0 || v > (NC - 1));
        if (tid == 0) s_is64 = (bad == 0u);
    }
    __syncthreads();

    const int is64 = s_is64;
    const int b    = (int)(blockIdx.x) / BPB;             // block-constant batch
    const int blkb = (int)(blockIdx.x) - b * BPB;
    const unsigned tid0 = (unsigned)blkb * TPB + tid;     // quad offset in batch

    const float4*    in4 = (const float4*)inp + (size_t)b * (NC * BQ);
    const int4*      tg4 = (const int4*)tgt + (size_t)b * BQ;
    const longlong2* tg8 = (const longlong2*)tgt + (size_t)b * BQ * 2;

    // byte-packed counters; byte (c-1) counts class c. <= 14*4 = 56 per byte.
    unsigned pp = 0u, tp = 0u, ip = 0u;

    #pragma unroll 4
    for (unsigned q = tid0; q < BQ; q += QSTRIDE) {
        // ---- targets: 4 positions ----
        int tv[4];
        if (is64) {
            longlong2 ta = tg8[2u * q];
            longlong2 tb = tg8[2u * q + 1u];
            tv[0] = (int)ta.x; tv[1] = (int)ta.y; tv[2] = (int)tb.x; tv[3] = (int)tb.y;
        } else {
            int4 t4 = tg4[q];
            tv[0] = t4.x; tv[1] = t4.y; tv[2] = t4.z; tv[3] = t4.w;
        }

        // ---- logits: 5 classes x float4 ----
        float va[NC][4];
        #pragma unroll
        for (int c = 0; c < NC; c++) {
            float4 v = in4[q + (unsigned)c * BQ];
            va[c][0] = v.x; va[c][1] = v.y; va[c][2] = v.z; va[c][3] = v.w;
        }

        // ---- per position: max + predicated packed increments ----
        #pragma unroll
        for (int k = 0; k < 4; k++) {
            const float f1 = va[1][k], f2 = va[2][k],
                        f3 = va[3][k], f4 = va[4][k];
            const float m = fmaxf(fmaxf(fmaxf(va[0][k], f1), fmaxf(f2, f3)), f4);
            const int t = tv[k];

            if (f1 == m) pp += 1u;
            if (f2 == m) pp += 1u << 8;
            if (f3 == m) pp += 1u << 16;
            if (f4 == m) pp += 1u << 24;

            if (t) tp += 1u << ((t - 1) * 8);

            if (f1 == m && t == 1) ip += 1u;
            if (f2 == m && t == 2) ip += 1u << 8;
            if (f3 == m && t == 3) ip += 1u << 16;
            if (f4 == m && t == 4) ip += 1u << 24;
        }
    }

    // warp reduction: bytes -> 16-bit fields (warp sum <= 1792), REDUX
    {
        unsigned v[6];
        v[0] = pp & 0x00FF00FFu;  v[1] = (pp >> 8) & 0x00FF00FFu;
        v[2] = tp & 0x00FF00FFu;  v[3] = (tp >> 8) & 0x00FF00FFu;
        v[4] = ip & 0x00FF00FFu;  v[5] = (ip >> 8) & 0x00FF00FFu;
        #pragma unroll
        for (int i = 0; i < 6; i++)
            v[i] = __reduce_add_sync(0xffffffffu, v[i]);
        if (lane == 0) {
            #pragma unroll
            for (int i = 0; i < 6; i++) atomicAdd(&s_pack[i], v[i]);
        }
    }
    __syncthreads();

    // block -> global: returning atomics (completion = L2 updated), no fence
    if (tid < 12) {
        const int kind = tid >> 2;            // 0=pred,1=tgt,2=inter
        const int ci   = tid & 3;             // class-1
        const unsigned pk = s_pack[kind * 2 + (ci & 1)];
        const int cnt = (int)((pk >> (16 * (ci >> 1))) & 0xFFFFu);
        const int ret = atomicAdd(&g_cnt[b * 12 + tid], cnt);
        s_sink[tid] = ret;                    // consume: waits for ATOMG return
    }
    __syncthreads();

    // last-block election (all 12 adds of every arrived block are L2-complete)
    if (tid == 0) s_last = (atomicAdd(&g_ticket, 1u) == NBLOCKS - 1);
    __syncthreads();

    if (s_last) {
        if (tid < NB * 12) {
            s_fin[tid] = atomicAdd(&g_cnt[tid], 0);   // L2-coherent read
            g_cnt[tid] = 0;                           // zero-at-entry invariant
        }
        if (tid == 0) g_ticket = 0u;
        __syncthreads();
        if (tid == 0) {
            float acc = 0.0f;
            #pragma unroll
            for (int bb = 0; bb < NB; bb++) {
                #pragma unroll
                for (int ci = 0; ci < 4; ci++) {
                    const float I = (float)s_fin[bb * 12 + 8 + ci];
                    const float U = (float)(s_fin[bb * 12 + ci] +
                                            s_fin[bb * 12 + 4 + ci]);
                    acc += (2.0f * I + 1e-5f) / (U + 1e-5f);
                }
            }
            out[0] = acc * (1.0f / 16.0f);
        }
    }
}

extern "C" void kernel_launch(void* const* d_in, const int* in_sizes, int n_in,
                              void* d_out, int out_size) {
    const float* inp = (const float*)d_in[0];
    const void*  tgt = d_in[1];
    float* out = (float*)d_out;
    (void)in_sizes; (void)n_in; (void)out_size;

    k_count<<<NBLOCKS, TPB>>>(inp, tgt, out);
}